// round 7
// baseline (speedup 1.0000x reference)
#include <cuda_runtime.h>
#include <cstdint>

#define NEG (-1e30f)
#define TLAST 512
#define NQ4 8404992          /* 513*65536/4 */
#define SCAN_SMEM 140032     /* 1KB vec + 4KB redf + 4KB redi + 130816B backtrack */

// ---------------- device globals (no allocations allowed) ----------------
__device__ float4 g_expM4[NQ4];          // exp(logM), 134.5 MB scratch
__device__ float g_la[514 * 256];
__device__ float g_lb[514 * 256];
__device__ float g_sa[2][256];           // alpha exchange (double-buffered)
__device__ float g_sb[2][256];           // beta exchange
__device__ float g_vd[2][256];           // viterbi exchange
__device__ __align__(16) unsigned char g_idx[511 * 256];
__device__ float g_logZ;

// ---------------- kernel 1: logM = sum_k w_k f[k] (masked) + expM ----------
__global__ void k_logM(const float4* __restrict__ f4,
                       const float* __restrict__ w,
                       float4* __restrict__ out) {
    __shared__ float sw[4];
    if (threadIdx.x < 4) sw[threadIdx.x] = w[threadIdx.x];
    __syncthreads();
    int e = blockIdx.x * blockDim.x + threadIdx.x;
    if (e >= NQ4) return;
    float4 a = f4[e];
    float4 b = f4[e + NQ4];
    float4 c = f4[e + 2 * NQ4];
    float4 d = f4[e + 3 * NQ4];
    float4 r;
    r.x = fmaf(sw[3], d.x, fmaf(sw[2], c.x, fmaf(sw[1], b.x, sw[0] * a.x)));
    r.y = fmaf(sw[3], d.y, fmaf(sw[2], c.y, fmaf(sw[1], b.y, sw[0] * a.y)));
    r.z = fmaf(sw[3], d.z, fmaf(sw[2], c.z, fmaf(sw[1], b.z, sw[0] * a.z)));
    r.w = fmaf(sw[3], d.w, fmaf(sw[2], c.w, fmaf(sw[1], b.w, sw[0] * a.w)));
    int t  = e >> 14;
    int q  = e & 16383;
    int i  = q >> 6;
    int j4 = q & 63;
    if (t == 0 && i != 0) { r.x = NEG; r.y = NEG; r.z = NEG; r.w = NEG; }
    if (t == TLAST) {
        if (j4 != 0) { r.x = NEG; r.y = NEG; r.z = NEG; r.w = NEG; }
        else         { r.y = NEG; r.z = NEG; r.w = NEG; }
    }
    float4 ex;
    ex.x = __expf(r.x); ex.y = __expf(r.y); ex.z = __expf(r.z); ex.w = __expf(r.w);
    out[e] = r;
    g_expM4[e] = ex;
}

// ---------------- cluster barrier ----------------
__device__ __forceinline__ void cluster_sync_all() {
    asm volatile("barrier.cluster.arrive.aligned;" ::: "memory");
    asm volatile("barrier.cluster.wait.aligned;" ::: "memory");
}

// ---------------- kernel 2: the three scans --------------------------------
// grid = 24 CTAs, cluster (8,1,1): cluster 0 = alpha, 1 = beta, 2 = viterbi
__global__ void __cluster_dims__(8, 1, 1) __launch_bounds__(256, 1)
k_scan(const float* __restrict__ lM, float* __restrict__ path_out) {
    extern __shared__ unsigned char smem_raw[];
    float* s_vec  = reinterpret_cast<float*>(smem_raw);          // 256 floats
    float* s_redf = s_vec + 256;                                 // 1024 floats
    int*   s_redi = reinterpret_cast<int*>(s_redf + 1024);       // 1024 ints
    unsigned char* s_bt = reinterpret_cast<unsigned char*>(s_redi + 1024);

    const int tid   = threadIdx.x;
    const int role  = blockIdx.x >> 3;
    const int crank = blockIdx.x & 7;

    if (role == 0) {
        // ============ forward alpha scan, linear (exp) space ============
        const int jq = tid & 7;
        const int ig = tid >> 3;
        const int jbase = crank * 32;
        s_vec[tid] = (tid == 0) ? 1.f : 0.f;   // exp(la0 - 0)
        if (crank == 0) g_la[tid] = (tid == 0) ? 0.f : NEG;
        float c = 0.f;
        __syncthreads();

        float4 tile[8];
        {
            const float4* p = g_expM4 + (jbase >> 2) + jq;
#pragma unroll
            for (int m = 0; m < 8; ++m) tile[m] = p[(ig * 8 + m) * 64];
        }
        for (int t = 0; t <= TLAST; ++t) {
            float ax = 0.f, ay = 0.f, az = 0.f, aw = 0.f;
#pragma unroll
            for (int m = 0; m < 8; ++m) {
                float a = s_vec[ig * 8 + m];
                ax = fmaf(a, tile[m].x, ax);
                ay = fmaf(a, tile[m].y, ay);
                az = fmaf(a, tile[m].z, az);
                aw = fmaf(a, tile[m].w, aw);
            }
            int col = jq * 4;
            s_redf[ig * 32 + col + 0] = ax;
            s_redf[ig * 32 + col + 1] = ay;
            s_redf[ig * 32 + col + 2] = az;
            s_redf[ig * 32 + col + 3] = aw;
            __syncthreads();
            if (tid < 32) {
                float s0 = 0.f, s1 = 0.f, s2 = 0.f, s3 = 0.f;
#pragma unroll
                for (int g = 0; g < 32; g += 4) {
                    s0 += s_redf[(g + 0) * 32 + tid];
                    s1 += s_redf[(g + 1) * 32 + tid];
                    s2 += s_redf[(g + 2) * 32 + tid];
                    s3 += s_redf[(g + 3) * 32 + tid];
                }
                float S = (s0 + s1) + (s2 + s3);
                g_sa[t & 1][jbase + tid] = S;
                g_la[(t + 1) * 256 + jbase + tid] = c + __logf(S);
            }
            if (t < TLAST) {   // prefetch next tile; completes during barrier
                const float4* p = g_expM4 + (size_t)(t + 1) * 16384 + (jbase >> 2) + jq;
#pragma unroll
                for (int m = 0; m < 8; ++m) tile[m] = p[(ig * 8 + m) * 64];
            }
            cluster_sync_all();
            float S0 = g_sa[t & 1][0];
            float St = g_sa[t & 1][tid];
            c += __logf(S0);
            s_vec[tid] = __fdividef(St, S0);
            __syncthreads();
        }
        if (crank == 0 && tid == 0) {
            float sum = 0.f;
            for (int j = 0; j < 256; ++j) sum += s_vec[j];
            g_logZ = c + __logf(sum);
        }
    } else if (role == 1) {
        // ============ backward beta scan, linear (exp) space ============
        const int jq = tid & 7;
        const int iloc = tid >> 3;
        const int ibase = crank * 32;
        s_vec[tid] = (tid == 0) ? 1.f : 0.f;
        if (crank == 0) g_lb[513 * 256 + tid] = (tid == 0) ? 0.f : NEG;
        float c = 0.f;
        __syncthreads();

        float4 tile[8];
        {
            const float4* p = g_expM4 + (size_t)TLAST * 16384 + (ibase + iloc) * 64;
#pragma unroll
            for (int m = 0; m < 8; ++m) tile[m] = p[jq + m * 8];
        }
        for (int t = TLAST; t >= 0; --t) {
            float acc = 0.f;
#pragma unroll
            for (int m = 0; m < 8; ++m) {
                const float4 b = *reinterpret_cast<const float4*>(s_vec + (jq + m * 8) * 4);
                acc = fmaf(tile[m].x, b.x, acc);
                acc = fmaf(tile[m].y, b.y, acc);
                acc = fmaf(tile[m].z, b.z, acc);
                acc = fmaf(tile[m].w, b.w, acc);
            }
            acc += __shfl_xor_sync(0xffffffffu, acc, 1);
            acc += __shfl_xor_sync(0xffffffffu, acc, 2);
            acc += __shfl_xor_sync(0xffffffffu, acc, 4);
            if (jq == 0) {
                g_sb[t & 1][ibase + iloc] = acc;
                g_lb[t * 256 + ibase + iloc] = c + __logf(acc);
            }
            if (t > 0) {
                const float4* p = g_expM4 + (size_t)(t - 1) * 16384 + (ibase + iloc) * 64;
#pragma unroll
                for (int m = 0; m < 8; ++m) tile[m] = p[jq + m * 8];
            }
            cluster_sync_all();
            float S0 = g_sb[t & 1][0];
            float St = g_sb[t & 1][tid];
            c += __logf(S0);
            s_vec[tid] = __fdividef(St, S0);
            __syncthreads();
        }
    } else {
        // ============ viterbi (max-plus, exact log space) + backtrack ============
        const int jq = tid & 7;
        const int ig = tid >> 3;
        const int jbase = crank * 32;
        s_vec[tid] = lM[tid];          // delta0 = logM[0, 0, :]
        __syncthreads();

        float4 tile[8];
        {
            const float4* p = reinterpret_cast<const float4*>(lM + 65536) + (jbase >> 2) + jq;
#pragma unroll
            for (int m = 0; m < 8; ++m) tile[m] = p[(ig * 8 + m) * 64];
        }
        for (int s = 1; s <= 511; ++s) {
            float ninf = -__int_as_float(0x7f800000);
            float bx = ninf, by = ninf, bz = ninf, bw = ninf;
            int ixx = 0, ixy = 0, ixz = 0, ixw = 0;
#pragma unroll
            for (int m = 0; m < 8; ++m) {
                int i = ig * 8 + m;
                float d = s_vec[i];
                float t0 = d + tile[m].x; if (t0 > bx) { bx = t0; ixx = i; }
                float t1 = d + tile[m].y; if (t1 > by) { by = t1; ixy = i; }
                float t2 = d + tile[m].z; if (t2 > bz) { bz = t2; ixz = i; }
                float t3 = d + tile[m].w; if (t3 > bw) { bw = t3; ixw = i; }
            }
            int col = jq * 4;
            s_redf[ig * 32 + col + 0] = bx; s_redi[ig * 32 + col + 0] = ixx;
            s_redf[ig * 32 + col + 1] = by; s_redi[ig * 32 + col + 1] = ixy;
            s_redf[ig * 32 + col + 2] = bz; s_redi[ig * 32 + col + 2] = ixz;
            s_redf[ig * 32 + col + 3] = bw; s_redi[ig * 32 + col + 3] = ixw;
            __syncthreads();
            if (tid < 32) {
                // 4 independent chains (ascending i within each), then ordered merge
                float v0, v1, v2, v3; int i0, i1, i2, i3;
                v0 = s_redf[0 * 32 + tid];  i0 = s_redi[0 * 32 + tid];
                v1 = s_redf[8 * 32 + tid];  i1 = s_redi[8 * 32 + tid];
                v2 = s_redf[16 * 32 + tid]; i2 = s_redi[16 * 32 + tid];
                v3 = s_redf[24 * 32 + tid]; i3 = s_redi[24 * 32 + tid];
#pragma unroll
                for (int g = 1; g < 8; ++g) {
                    float a0 = s_redf[(g + 0)  * 32 + tid];
                    float a1 = s_redf[(g + 8)  * 32 + tid];
                    float a2 = s_redf[(g + 16) * 32 + tid];
                    float a3 = s_redf[(g + 24) * 32 + tid];
                    if (a0 > v0) { v0 = a0; i0 = s_redi[(g + 0)  * 32 + tid]; }
                    if (a1 > v1) { v1 = a1; i1 = s_redi[(g + 8)  * 32 + tid]; }
                    if (a2 > v2) { v2 = a2; i2 = s_redi[(g + 16) * 32 + tid]; }
                    if (a3 > v3) { v3 = a3; i3 = s_redi[(g + 24) * 32 + tid]; }
                }
                if (v1 > v0) { v0 = v1; i0 = i1; }   // strict > keeps lowest i on ties
                if (v2 > v0) { v0 = v2; i0 = i2; }
                if (v3 > v0) { v0 = v3; i0 = i3; }
                g_vd[s & 1][jbase + tid] = v0;
                g_idx[(s - 1) * 256 + jbase + tid] = (unsigned char)i0;
            }
            if (s < 511) {
                const float4* p = reinterpret_cast<const float4*>(lM + (size_t)(s + 1) * 65536)
                                  + (jbase >> 2) + jq;
#pragma unroll
                for (int m = 0; m < 8; ++m) tile[m] = p[(ig * 8 + m) * 64];
            }
            cluster_sync_all();
            s_vec[tid] = g_vd[s & 1][tid];
            __syncthreads();
        }
        // backtrack on cluster rank 0 (table copied to SMEM)
        if (crank == 0) {
            const uint32_t* src = reinterpret_cast<const uint32_t*>(g_idx);
            uint32_t* dst = reinterpret_cast<uint32_t*>(s_bt);
            for (int k = tid; k < (511 * 256) / 4; k += 256) dst[k] = src[k];
            __syncthreads();
            if (tid == 0) {
                float bv = s_vec[0];
                int li = 0;
                for (int j = 1; j < 256; ++j) {
                    float v = s_vec[j];
                    if (v > bv) { bv = v; li = j; }
                }
                path_out[511] = (float)li;
                int y = li;
                for (int s2 = 510; s2 >= 0; --s2) {
                    y = s_bt[s2 * 256 + y];
                    path_out[s2] = (float)y;
                }
            }
        }
    }
}

// ---------------- kernel 3: p12 = expM * exp(la + lb - logZ) ----------------
__global__ void k_p12(float4* __restrict__ m) {
    int e = blockIdx.x * blockDim.x + threadIdx.x;
    if (e >= NQ4) return;
    int t  = e >> 14;
    int q  = e & 16383;
    int i  = q >> 6;
    int j4 = q & 63;
    float4 v = g_expM4[e];
    float A = g_la[t * 256 + i] - g_logZ;
    const float4 B = *reinterpret_cast<const float4*>(&g_lb[(t + 1) * 256 + j4 * 4]);
    float4 r;
    r.x = v.x * __expf(A + B.x);
    r.y = v.y * __expf(A + B.y);
    r.z = v.z * __expf(A + B.z);
    r.w = v.w * __expf(A + B.w);
    m[e] = r;
}

// ---------------- launcher ----------------
extern "C" void kernel_launch(void* const* d_in, const int* in_sizes, int n_in,
                              void* d_out, int out_size) {
    const float* f = (const float*)d_in[0];
    const float* w = (const float*)d_in[1];
    float* out = (float*)d_out;

    cudaFuncSetAttribute(k_scan, cudaFuncAttributeMaxDynamicSharedMemorySize, SCAN_SMEM);

    const int nb = (NQ4 + 255) / 256;   // 32832
    k_logM<<<nb, 256>>>((const float4*)f, w, (float4*)out);
    k_scan<<<24, 256, SCAN_SMEM>>>(out, out + (out_size - 512));
    k_p12<<<nb, 256>>>((float4*)out);
}